// round 12
// baseline (speedup 1.0000x reference)
#include <cuda_runtime.h>
#include <cuda_bf16.h>

// WaveletTransformLayer: x (B=128, T=2048, F=32) f32.
// Per (b,f): d1 (2047) | d2 (2044) | d3 (2037) | ma3 (2037), each / T.
// Collapsed FIR taps over x[t..t+11]:
//   d1[t] = (x1-x0)/2 ; ma2 = [1,2,2,2,1]/8 ; ma3 = [1,3,5,7,8,8,8,8,7,5,3,1]/64
//   d2[t] = (x3+x4)/2 - ma2[t] ; d3[t] = ma2[t+7] - ma3[t]
//
// R12: R11 geometry (512 thr = t:128 x fq:4, 3 blocks/SM, persistent 444) with
//  (a) LDS.128 compute: PITCH=36, thread reads 12 float4 = 4 features/pass
//      (quad-bank (9t+f/4) mod 8 distinct per 8-lane phase -> conflict-free)
//  (b) cp.async double-buffered tile fill: next unit's LDGSTS overlaps current
//      unit's compute, hiding DRAM latency at unit boundaries.

#define T_LEN   2048
#define F_DIM   32
#define TT      128
#define NTILES  (T_LEN / TT)     // 16
#define NUNITS  (NTILES * 128)   // 2048
#define HALO    12
#define LOADT   (TT + HALO)      // 140
#define PITCH   36               // LDS.128 / cp.async 16B conflict-free
#define BUFSZ   (LOADT * PITCH)  // 5040 floats = 20160 B
#define OUT_PER_F 8165
#define SEG1    2047
#define SEG2    4091
#define SEG3    6128
#define LIM1    2047
#define LIM2    2044
#define LIM3    2037

#define NSM     148
#define BLKSM   3
#define GRID    (NSM * BLKSM)    // 444
#define NTHR    512

__device__ __forceinline__ void issue_fill(const float* __restrict__ base,
                                           int t0, int tid, float* dst) {
    #pragma unroll
    for (int k = 0; k < 3; ++k) {
        int i = tid + k * NTHR;
        if (i < LOADT * 8) {                 // 1120 vec4s
            int tt = i >> 3;
            int f4 = (i & 7) << 2;
            int tg = t0 + tt; if (tg > T_LEN - 1) tg = T_LEN - 1;  // clamp: unused if OOB
            const float* src = base + (size_t)tg * F_DIM + f4;
            unsigned sdst = (unsigned)__cvta_generic_to_shared(dst + tt * PITCH + f4);
            asm volatile("cp.async.ca.shared.global [%0], [%1], 16;\n"
                         :: "r"(sdst), "l"(src));
        }
    }
    asm volatile("cp.async.commit_group;\n" ::: "memory");
}

__global__ __launch_bounds__(NTHR, BLKSM)
void wavelet_kernel(const float* __restrict__ x, float* __restrict__ out) {
    __shared__ float xs[2 * BUFSZ];       // 40320 B

    const int tid = threadIdx.x;          // 0..511
    const int t   = tid & 127;            // lane-contiguous t within warp
    const int f0  = (tid >> 7) << 3;      // 8 features per thread (2 passes of 4)

    const float inv   = 1.0f / 2048.0f;
    const float inv2  = inv * 0.5f;
    const float inv8  = inv * 0.125f;
    const float inv64 = inv * 0.015625f;

    // Prologue: prefetch first unit into buffer 0
    {
        const int u0 = blockIdx.x;
        const int b0 = u0 >> 4;
        issue_fill(x + (size_t)b0 * (T_LEN * F_DIM), (u0 & (NTILES - 1)) * TT, tid, xs);
    }

    int buf = 0;
    for (int u = blockIdx.x; u < NUNITS; u += GRID) {
        // Prefetch next unit into the other buffer (clamped; extra group is harmless)
        {
            int un = u + GRID; if (un >= NUNITS) un = u;
            const int bn = un >> 4;
            issue_fill(x + (size_t)bn * (T_LEN * F_DIM), (un & (NTILES - 1)) * TT,
                       tid, xs + (buf ^ 1) * BUFSZ);
        }
        asm volatile("cp.async.wait_group 1;\n" ::: "memory");  // current buffer ready
        __syncthreads();

        const int tile = u & (NTILES - 1);
        const int b    = u >> 4;
        const int t0   = tile * TT;
        const int tg   = t0 + t;
        const float* sb = xs + buf * BUFSZ;
        float* outb = out + (size_t)b * (F_DIM * OUT_PER_F);

        const bool full = (tile != NTILES - 1);
        const bool w1 = full || (tg < LIM1);
        const bool w2 = full || (tg < LIM2);
        const bool w3 = full || (tg < LIM3);

        #pragma unroll
        for (int g = 0; g < 2; ++g) {
            const int f = f0 + 4 * g;
            const float* s = sb + t * PITCH + f;
            float4 q[12];
            #pragma unroll
            for (int j = 0; j < 12; ++j)
                q[j] = *(const float4*)(s + j * PITCH);   // LDS.128, conflict-free
            const float* qa = (const float*)q;            // qa[4*j + c]

            #pragma unroll
            for (int c = 0; c < 4; ++c) {
                float x0  = qa[c],      x1  = qa[4  + c], x2  = qa[8  + c];
                float x3  = qa[12 + c], x4  = qa[16 + c], x5  = qa[20 + c];
                float x6  = qa[24 + c], x7  = qa[28 + c], x8  = qa[32 + c];
                float x9  = qa[36 + c], x10 = qa[40 + c], x11 = qa[44 + c];

                float d1  = (x1 - x0) * inv2;
                float m2a = x0 + x4 + 2.0f * (x1 + x2 + x3);
                float d2  = (x3 + x4) * inv2 - m2a * inv8;
                float m2b = x7 + x11 + 2.0f * (x8 + x9 + x10);
                float m3  = (x0 + x11) + 3.0f * (x1 + x10) + 5.0f * (x2 + x9)
                          + 7.0f * (x3 + x8) + 8.0f * (x4 + x5 + x6 + x7);
                float d3  = m2b * inv8 - m3 * inv64;
                float ma3 = m3 * inv64;

                float* of = outb + (size_t)(f + c) * OUT_PER_F;
                if (w1) of[tg]        = d1;
                if (w2) of[SEG1 + tg] = d2;
                if (w3) {
                    of[SEG2 + tg] = d3;
                    of[SEG3 + tg] = ma3;
                }
            }
        }
        __syncthreads();   // block done with sb before it is refilled next round
        buf ^= 1;
    }
}

extern "C" void kernel_launch(void* const* d_in, const int* in_sizes, int n_in,
                              void* d_out, int out_size) {
    const float* x = (const float*)d_in[0];
    float* out = (float*)d_out;
    wavelet_kernel<<<GRID, NTHR>>>(x, out);
}

// round 14
// speedup vs baseline: 1.8906x; 1.8906x over previous
#include <cuda_runtime.h>
#include <cuda_bf16.h>

// WaveletTransformLayer: x (B=128, T=2048, F=32) f32.
// Per (b,f): d1 (2047) | d2 (2044) | d3 (2037) | ma3 (2037), each / T.
// Collapsed FIR taps over x[t..t+11]:
//   d1[t] = (x1-x0)/2 ; ma2 = [1,2,2,2,1]/8 ; ma3 = [1,3,5,7,8,8,8,8,7,5,3,1]/64
//   d2[t] = (x3+x4)/2 - ma2[t] ; d3[t] = ma2[t+7] - ma3[t]
//
// R14 = R13 rerun (infra failure last round): R11 inner loop + DRAM-stream
// policy test:
//   (1) bounded block-start prefetch.global.L2 of the first 6 units' slabs
//   (2) st.global.cs (evict-first) on all output stores
// Hypothesis: flat ~36.7us across R5-R12 is DRAM read/write-mix efficiency
// (~3TB/s effective), not an SM-side limit.

#define T_LEN   2048
#define F_DIM   32
#define TT      128
#define NTILES  (T_LEN / TT)     // 16
#define NUNITS  (NTILES * 128)   // 2048
#define HALO    12
#define LOADT   (TT + HALO)      // 140
#define PITCH   33               // conflict-free for STS.32 fill and LDS.32 compute
#define OUT_PER_F 8165
#define SEG1    2047
#define SEG2    4091
#define SEG3    6128
#define LIM1    2047
#define LIM2    2044
#define LIM3    2037

#define NSM     148
#define BLKSM   3
#define GRID    (NSM * BLKSM)    // 444
#define NTHR    512
#define PFU     6                // units prefetched per block at start

__device__ __forceinline__ void stcs(float* p, float v) {
    asm volatile("st.global.cs.f32 [%0], %1;" :: "l"(p), "f"(v) : "memory");
}
__device__ __forceinline__ void l2pf(const void* p) {
    asm volatile("prefetch.global.L2 [%0];" :: "l"(p));
}

__global__ __launch_bounds__(NTHR, BLKSM)
void wavelet_kernel(const float* __restrict__ x, float* __restrict__ out) {
    __shared__ float xs[LOADT * PITCH];   // 140*33*4 = 18480 B

    const int tid = threadIdx.x;          // 0..511
    const int t   = tid & 127;            // lane-contiguous t within warp
    const int f0  = (tid >> 7) << 3;      // f-quarter base: 8 features per thread

    // ---- Phase 0: prefetch the first PFU units' input slabs into L2 ----
    // Unit slab: 140 lines of 128B starting at a 128B-aligned offset.
    {
        int n = 0;
        for (int u = blockIdx.x; u < NUNITS && n < PFU; u += GRID, ++n) {
            const int b  = u >> 4;
            const int t0 = (u & (NTILES - 1)) * TT;
            const char* slab = (const char*)(x + (size_t)b * (T_LEN * F_DIM)
                                               + (size_t)t0 * F_DIM);
            #pragma unroll 1
            for (int i = tid; i < LOADT; i += NTHR)
                l2pf(slab + (size_t)i * 128);
        }
    }

    const float inv   = 1.0f / 2048.0f;
    const float inv2  = inv * 0.5f;
    const float inv8  = inv * 0.125f;
    const float inv64 = inv * 0.015625f;

    for (int u = blockIdx.x; u < NUNITS; u += GRID) {
        const int tile = u & (NTILES - 1);   // 0..15
        const int b    = u >> 4;             // 0..127
        const int t0   = tile * TT;

        // ---- Fill: LDG.128 (t-major, f contiguous) -> 4x STS.32, conflict-free ----
        const float4* gsrc = (const float4*)(x + (size_t)b * (T_LEN * F_DIM)
                                               + (size_t)t0 * F_DIM);
        if (tile != NTILES - 1) {
            #pragma unroll
            for (int k = 0; k < 3; ++k) {
                int i = tid + k * NTHR;
                if (i < LOADT * 8) {          // 1120 vec4s
                    int tt = i >> 3;
                    int f4 = (i & 7) << 2;
                    float4 v = gsrc[i];
                    float* d = &xs[tt * PITCH + f4];
                    d[0] = v.x; d[1] = v.y; d[2] = v.z; d[3] = v.w;
                }
            }
        } else {
            #pragma unroll
            for (int k = 0; k < 3; ++k) {
                int i = tid + k * NTHR;
                if (i < LOADT * 8) {
                    int tt = i >> 3;
                    int f4 = (i & 7) << 2;
                    float4 v = make_float4(0.f, 0.f, 0.f, 0.f);
                    if (t0 + tt < T_LEN) v = gsrc[i];
                    float* d = &xs[tt * PITCH + f4];
                    d[0] = v.x; d[1] = v.y; d[2] = v.z; d[3] = v.w;
                }
            }
        }
        __syncthreads();

        // ---- Compute: thread = t (lane-contiguous -> coalesced stores), 8 f each ----
        const int tg = t0 + t;
        float* outb = out + (size_t)b * (F_DIM * OUT_PER_F) + (size_t)f0 * OUT_PER_F;

        if (tile != NTILES - 1) {   // tiles 0..14: all stores unconditional
            #pragma unroll 2
            for (int fi = 0; fi < 8; ++fi) {
                const float* s = xs + t * PITCH + f0 + fi;
                float x0  = s[0 * PITCH],  x1 = s[1 * PITCH],  x2  = s[2 * PITCH];
                float x3  = s[3 * PITCH],  x4 = s[4 * PITCH],  x5  = s[5 * PITCH];
                float x6  = s[6 * PITCH],  x7 = s[7 * PITCH],  x8  = s[8 * PITCH];
                float x9  = s[9 * PITCH], x10 = s[10 * PITCH], x11 = s[11 * PITCH];

                float d1  = (x1 - x0) * inv2;
                float m2a = x0 + x4 + 2.0f * (x1 + x2 + x3);
                float d2  = (x3 + x4) * inv2 - m2a * inv8;
                float m2b = x7 + x11 + 2.0f * (x8 + x9 + x10);
                float m3  = (x0 + x11) + 3.0f * (x1 + x10) + 5.0f * (x2 + x9)
                          + 7.0f * (x3 + x8) + 8.0f * (x4 + x5 + x6 + x7);
                float d3  = m2b * inv8 - m3 * inv64;
                float ma3 = m3 * inv64;

                float* of = outb + (size_t)fi * OUT_PER_F;
                stcs(of + tg,        d1);
                stcs(of + SEG1 + tg, d2);
                stcs(of + SEG2 + tg, d3);
                stcs(of + SEG3 + tg, ma3);
            }
        } else {                    // tile 15: predicated stores
            const bool w1 = (tg < LIM1);
            const bool w2 = (tg < LIM2);
            const bool w3 = (tg < LIM3);
            #pragma unroll 2
            for (int fi = 0; fi < 8; ++fi) {
                const float* s = xs + t * PITCH + f0 + fi;
                float x0  = s[0 * PITCH],  x1 = s[1 * PITCH],  x2  = s[2 * PITCH];
                float x3  = s[3 * PITCH],  x4 = s[4 * PITCH],  x5  = s[5 * PITCH];
                float x6  = s[6 * PITCH],  x7 = s[7 * PITCH],  x8  = s[8 * PITCH];
                float x9  = s[9 * PITCH], x10 = s[10 * PITCH], x11 = s[11 * PITCH];

                float d1  = (x1 - x0) * inv2;
                float m2a = x0 + x4 + 2.0f * (x1 + x2 + x3);
                float d2  = (x3 + x4) * inv2 - m2a * inv8;
                float m2b = x7 + x11 + 2.0f * (x8 + x9 + x10);
                float m3  = (x0 + x11) + 3.0f * (x1 + x10) + 5.0f * (x2 + x9)
                          + 7.0f * (x3 + x8) + 8.0f * (x4 + x5 + x6 + x7);
                float d3  = m2b * inv8 - m3 * inv64;
                float ma3 = m3 * inv64;

                float* of = outb + (size_t)fi * OUT_PER_F;
                if (w1) stcs(of + tg,        d1);
                if (w2) stcs(of + SEG1 + tg, d2);
                if (w3) {
                    stcs(of + SEG2 + tg, d3);
                    stcs(of + SEG3 + tg, ma3);
                }
            }
        }
        __syncthreads();   // protect smem reuse across grid-stride iterations
    }
}

extern "C" void kernel_launch(void* const* d_in, const int* in_sizes, int n_in,
                              void* d_out, int out_size) {
    const float* x = (const float*)d_in[0];
    float* out = (float*)d_out;
    wavelet_kernel<<<GRID, NTHR>>>(x, out);
}